// round 16
// baseline (speedup 1.0000x reference)
#include <cuda_runtime.h>
#include <cuda_fp16.h>
#include <cstdint>

// Problem constants
#define B_ 4
#define S_ 2048
#define D_ 1024
#define H_ 16
#define DK_ 64
#define QSCALE_ 0.1803368801111137f   // (1/sqrt(64)) * log2(e)

#define M_ROWS (B_ * S_)   // 8192

// ---------------- scratch (device globals; no allocation allowed) ----------
__device__ __half g_wq[D_ * D_];     // transposed [N][K]
__device__ __half g_wk[D_ * D_];
__device__ __half g_wv[D_ * D_];
__device__ __half g_wo[D_ * D_];
__device__ __half g_q[B_ * H_ * S_ * DK_];    // [B,H,S,DK], pre-scaled by QSCALE_
__device__ __half g_k[B_ * H_ * S_ * DK_];    // [B,H,S,DK]
__device__ __half g_vt[B_ * H_ * DK_ * S_];   // [B,H,DK,S]  (transposed V)
__device__ __half g_att[B_ * S_ * D_];        // [B,S,D]

// ---------------- helpers -----------------------------------------------------
__device__ __forceinline__ void mma_f16_16x8x16(
    float& c0, float& c1, float& c2, float& c3,
    uint32_t a0, uint32_t a1, uint32_t a2, uint32_t a3,
    uint32_t b0, uint32_t b1)
{
    asm volatile(
        "mma.sync.aligned.m16n8k16.row.col.f32.f16.f16.f32 "
        "{%0,%1,%2,%3}, {%4,%5,%6,%7}, {%8,%9}, {%0,%1,%2,%3};"
        : "+f"(c0), "+f"(c1), "+f"(c2), "+f"(c3)
        : "r"(a0), "r"(a1), "r"(a2), "r"(a3), "r"(b0), "r"(b1));
}

// fp16-accumulate variant: c0 = {row lr, cols 2lc,2lc+1}, c1 = {row lr+8, same}
__device__ __forceinline__ void mma_f16acc_16x8x16(
    uint32_t& c0, uint32_t& c1,
    uint32_t a0, uint32_t a1, uint32_t a2, uint32_t a3,
    uint32_t b0, uint32_t b1)
{
    asm volatile(
        "mma.sync.aligned.m16n8k16.row.col.f16.f16.f16.f16 "
        "{%0,%1}, {%2,%3,%4,%5}, {%6,%7}, {%0,%1};"
        : "+r"(c0), "+r"(c1)
        : "r"(a0), "r"(a1), "r"(a2), "r"(a3), "r"(b0), "r"(b1));
}

__device__ __forceinline__ void ldsm_x4(uint32_t& r0, uint32_t& r1,
                                        uint32_t& r2, uint32_t& r3, uint32_t a)
{
    asm volatile("ldmatrix.sync.aligned.m8n8.x4.shared.b16 {%0,%1,%2,%3}, [%4];"
                 : "=r"(r0), "=r"(r1), "=r"(r2), "=r"(r3) : "r"(a));
}

__device__ __forceinline__ void cp_async16(uint32_t smem_dst, const void* gsrc) {
    asm volatile("cp.async.cg.shared.global [%0], [%1], 16;"
                 :: "r"(smem_dst), "l"(gsrc));
}
__device__ __forceinline__ void cp_commit() {
    asm volatile("cp.async.commit_group;");
}
__device__ __forceinline__ void cp_wait0() {
    asm volatile("cp.async.wait_group 0;");
}
__device__ __forceinline__ uint32_t smaddr(const void* p) {
    return (uint32_t)__cvta_generic_to_shared(p);
}
__device__ __forceinline__ uint32_t h2u(__half2 h) {
    return *(uint32_t*)&h;
}
__device__ __forceinline__ __half2 u2h(uint32_t u) {
    return *(__half2*)&u;
}
__device__ __forceinline__ float fexp2(float x) {
    float y;
    asm("ex2.approx.f32 %0, %1;" : "=f"(y) : "f"(x));
    return y;
}
// ex2 on packed half2 (1 MUFU op for 2 values)
__device__ __forceinline__ uint32_t exh2(uint32_t u) {
    asm("ex2.approx.f16x2 %0, %0;" : "+r"(u));
    return u;
}
__device__ __forceinline__ uint32_t hadd2u(uint32_t a, uint32_t b) {
    return h2u(__hadd2(u2h(a), u2h(b)));
}

// ---------------- fused fp32 [K][N] -> fp16 transposed [N][K] (4 weights) ------
__global__ __launch_bounds__(256)
void convT_w4_kernel(const float* __restrict__ W0, const float* __restrict__ W1,
                     const float* __restrict__ W2, const float* __restrict__ W3,
                     __half* __restrict__ T0, __half* __restrict__ T1,
                     __half* __restrict__ T2, __half* __restrict__ T3)
{
    __shared__ float t[32][33];
    const float* W = blockIdx.z == 0 ? W0 : (blockIdx.z == 1 ? W1 :
                     (blockIdx.z == 2 ? W2 : W3));
    __half* Wt     = blockIdx.z == 0 ? T0 : (blockIdx.z == 1 ? T1 :
                     (blockIdx.z == 2 ? T2 : T3));
    const int bn = blockIdx.x * 32;
    const int bk = blockIdx.y * 32;
    const int x = threadIdx.x;
    #pragma unroll
    for (int y = threadIdx.y; y < 32; y += 8)
        t[y][x] = W[(size_t)(bk + y) * D_ + bn + x];
    __syncthreads();
    #pragma unroll
    for (int y = threadIdx.y; y < 32; y += 8)
        Wt[(size_t)(bn + y) * D_ + bk + x] = __float2half(t[x][y]);
}

// ---------------- fp16 tensor-core GEMM core (cp.async + ldmatrix) -------------
// C = A[M,K] @ Wt[N,K]^T + bias.  (128x128, 256 threads; fp32 accumulate)
// ASRC 0: A is fp16 (cp.async path).  ASRC 1: A is fp32, converted inline
// during the A-tile smem store (LDG.128 -> F2FP.PACK -> STS.128).
// mode 0: float* row-major [M,N]; mode 1: half* [B,H,S,DK]*out_scale;
// mode 2: half* [B,H,DK,S].
#define GBKH 32                 // K per stage, in halves
#define G_STR 20                // row stride in uint32(half2) units
#define G_WORDS (128 * G_STR)

template <int ASRC>
__device__ __forceinline__
void gemm_f16_body(const void* __restrict__ Ain, const __half* __restrict__ Wt,
                   const float* __restrict__ bias, void* __restrict__ Cout,
                   int mode, float out_scale,
                   uint32_t* As, uint32_t* Bs)
{
    const int K = D_, N = D_;
    const int tid  = threadIdx.x;
    const int warp = tid >> 5;
    const int lane = tid & 31;
    const int warpM = warp >> 2;
    const int warpN = warp & 3;
    const int lr = lane >> 2;
    const int lc = lane & 3;

    // ldmatrix lane->address selectors
    const int arow = ((lane >> 3) & 1) * 8 + (lane & 7);
    const int acol = ((lane >> 4) & 1) * 4;
    const int brow = ((lane >> 4) & 1) * 8 + (lane & 7);
    const int bcol = ((lane >> 3) & 1) * 4;

    const int block_row = blockIdx.y;
    const int block_col = blockIdx.x;

    const __half* Ah = (const __half*)Ain + (size_t)block_row * 128 * K;
    const float*  Af = (const float*)Ain  + (size_t)block_row * 128 * K;
    const __half* Wb = Wt + (size_t)block_col * 128 * K;

    float acc[4][4][4];
    #pragma unroll
    for (int mt = 0; mt < 4; mt++)
        #pragma unroll
        for (int nt = 0; nt < 4; nt++)
            #pragma unroll
            for (int r = 0; r < 4; r++) acc[mt][nt][r] = 0.f;

    auto load_stage = [&](int k0, int buf) {
        uint32_t* Ad = As + buf * G_WORDS;
        uint32_t* Bd = Bs + buf * G_WORDS;
        #pragma unroll
        for (int u = 0; u < 2; u++) {
            const int flat = tid + u * 256;
            const int r = flat >> 2;
            const int c = (flat & 3);
            if (ASRC == 0) {
                cp_async16(smaddr(Ad + r * G_STR + c * 4),
                           Ah + (size_t)r * K + k0 + c * 8);
            } else {
                const float* src = Af + (size_t)r * K + k0 + c * 8;
                const float4 f0 = *(const float4*)(src);
                const float4 f1 = *(const float4*)(src + 4);
                uint4 w;
                w.x = h2u(__floats2half2_rn(f0.x, f0.y));
                w.y = h2u(__floats2half2_rn(f0.z, f0.w));
                w.z = h2u(__floats2half2_rn(f1.x, f1.y));
                w.w = h2u(__floats2half2_rn(f1.z, f1.w));
                *(uint4*)(Ad + r * G_STR + c * 4) = w;
            }
            cp_async16(smaddr(Bd + r * G_STR + c * 4), Wb + (size_t)r * K + k0 + c * 8);
        }
    };

    const int NK = K / GBKH;
    load_stage(0, 0);
    cp_commit();

    for (int it = 0; it < NK; it++) {
        cp_wait0();
        __syncthreads();
        if (it + 1 < NK) { load_stage((it + 1) * GBKH, (it + 1) & 1); cp_commit(); }

        const uint32_t* As_s = As + (it & 1) * G_WORDS;
        const uint32_t* Bs_s = Bs + (it & 1) * G_WORDS;

        #pragma unroll
        for (int ch = 0; ch < 2; ch++) {
            const int ks2 = ch * 8;
            uint32_t af[4][4];
            #pragma unroll
            for (int mt = 0; mt < 4; mt++) {
                const int m0 = warpM * 64 + mt * 16;
                ldsm_x4(af[mt][0], af[mt][1], af[mt][2], af[mt][3],
                        smaddr(&As_s[(m0 + arow) * G_STR + ks2 + acol]));
            }
            uint32_t bf[4][2];
            #pragma unroll
            for (int np = 0; np < 2; np++) {
                const int n0 = warpN * 32 + np * 16;
                ldsm_x4(bf[np * 2][0], bf[np * 2][1], bf[np * 2 + 1][0], bf[np * 2 + 1][1],
                        smaddr(&Bs_s[(n0 + brow) * G_STR + ks2 + bcol]));
            }
            #pragma unroll
            for (int mt = 0; mt < 4; mt++)
                #pragma unroll
                for (int nt = 0; nt < 4; nt++)
                    mma_f16_16x8x16(acc[mt][nt][0], acc[mt][nt][1],
                                    acc[mt][nt][2], acc[mt][nt][3],
                                    af[mt][0], af[mt][1], af[mt][2], af[mt][3],
                                    bf[nt][0], bf[nt][1]);
        }
    }

    #pragma unroll
    for (int mt = 0; mt < 4; mt++) {
        #pragma unroll
        for (int nt = 0; nt < 4; nt++) {
            const int n = block_col * 128 + warpN * 32 + nt * 8 + lc * 2;
            #pragma unroll
            for (int half_ = 0; half_ < 2; half_++) {
                const int m = block_row * 128 + warpM * 64 + mt * 16 + lr + half_ * 8;
                const float v0 = acc[mt][nt][half_ * 2 + 0] + bias[n];
                const float v1 = acc[mt][nt][half_ * 2 + 1] + bias[n + 1];
                if (mode == 0) {
                    float* C = (float*)Cout;
                    *(float2*)&C[(size_t)m * N + n] = make_float2(v0, v1);
                } else {
                    const int b  = m >> 11;
                    const int s  = m & 2047;
                    const int h  = n >> 6;
                    const int dk = n & 63;
                    __half* C = (__half*)Cout;
                    if (mode == 1) {
                        *(__half2*)(C + (((size_t)(b * H_ + h)) * S_ + s) * DK_ + dk)
                            = __floats2half2_rn(v0 * out_scale, v1 * out_scale);
                    } else {
                        C[(((size_t)(b * H_ + h)) * DK_ + dk)     * S_ + s] = __float2half(v0);
                        C[(((size_t)(b * H_ + h)) * DK_ + dk + 1) * S_ + s] = __float2half(v1);
                    }
                }
            }
        }
    }
}

// fused QKV projections (grid.z selects tensor); A inputs are fp32 (inline cvt)
__global__ __launch_bounds__(256)
void gemm_qkv_kernel(const float* __restrict__ Qin, const float* __restrict__ Kin,
                     const float* __restrict__ Vin,
                     const __half* __restrict__ wq, const __half* __restrict__ wk,
                     const __half* __restrict__ wv,
                     const float* __restrict__ bq, const float* __restrict__ bk,
                     const float* __restrict__ bv,
                     __half* __restrict__ q, __half* __restrict__ k,
                     __half* __restrict__ vt)
{
    __shared__ uint32_t As[2 * G_WORDS];
    __shared__ uint32_t Bs[2 * G_WORDS];
    const int z = blockIdx.z;
    if (z == 0)      gemm_f16_body<1>(Qin, wq, bq, q,  1, QSCALE_, As, Bs);
    else if (z == 1) gemm_f16_body<1>(Kin, wk, bk, k,  1, 1.0f,    As, Bs);
    else             gemm_f16_body<1>(Vin, wv, bv, vt, 2, 1.0f,    As, Bs);
}

// output projection (A = fp16 attention output)
__global__ __launch_bounds__(256)
void gemm_out_kernel(const __half* __restrict__ att, const __half* __restrict__ wo,
                     const float* __restrict__ bo, float* __restrict__ out)
{
    __shared__ uint32_t As[2 * G_WORDS];
    __shared__ uint32_t Bs[2 * G_WORDS];
    gemm_f16_body<0>(att, wo, bo, out, 0, 1.0f, As, Bs);
}

// ---------------- fp16 tensor-core causal flash attention ----------------------
// 128 q-rows per block, 8 warps x 16 rows, double-buffered 64-key K / V^T tiles.
// QK accumulates fp16; softmax in half2; PV accumulates fp32.
// Warps skip key tiles above their diagonal band.  (exact R12 form)
#define FSTR 36                  // 32 half2 + 4 pad
#define FTILE (64 * FSTR)

__global__ __launch_bounds__(256, 2)
void flash_attn_f16_kernel(const __half* __restrict__ q, const __half* __restrict__ k,
                           const __half* __restrict__ vt, __half* __restrict__ o)
{
    __shared__ uint32_t KsBuf[2][FTILE];     // also used (contiguously) to stage Q
    __shared__ uint32_t VtBuf[2][FTILE];

    const int qt  = gridDim.x - 1 - blockIdx.x;   // big blocks first
    const int bh  = blockIdx.y;
    const int tid = threadIdx.x;
    const int warp = tid >> 5;
    const int lane = tid & 31;
    const int lr = lane >> 2;
    const int lc = lane & 3;
    const int q0 = qt * 128;
    const int mb = warp * 16;

    // ldmatrix B-operand lane selectors
    const int brow = ((lane >> 4) & 1) * 8 + (lane & 7);
    const int bcol = ((lane >> 3) & 1) * 4;

    const __half* qb  = q  + (size_t)bh * S_ * DK_;
    const __half* kb  = k  + (size_t)bh * S_ * DK_;
    const __half* vtb = vt + (size_t)bh * DK_ * S_;

    // ---- stage Q tile (128x64h = 4608 words) across KsBuf[0..1]; 4 chunks/thr --
    uint32_t* Qs = &KsBuf[0][0];
    #pragma unroll
    for (int i = 0; i < 4; i++) {
        const int flat = tid + 256 * i;           // 0..1023
        const int row = flat >> 3;
        const int c = flat & 7;
        cp_async16(smaddr(Qs + row * FSTR + c * 4),
                   qb + (size_t)(q0 + row) * DK_ + c * 8);
    }
    cp_commit();
    cp_wait0();
    __syncthreads();

    uint32_t qf[4][4];
    #pragma unroll
    for (int i = 0; i < 4; i++) {
        qf[i][0] = Qs[(mb + lr)     * FSTR + 8 * i + lc];
        qf[i][1] = Qs[(mb + 8 + lr) * FSTR + 8 * i + lc];
        qf[i][2] = Qs[(mb + lr)     * FSTR + 8 * i + 4 + lc];
        qf[i][3] = Qs[(mb + 8 + lr) * FSTR + 8 * i + 4 + lc];
    }
    __syncthreads();   // Q reads done before K tiles overwrite

    float oacc[8][4];
    #pragma unroll
    for (int nt = 0; nt < 8; nt++)
        #pragma unroll
        for (int c = 0; c < 4; c++) oacc[nt][c] = 0.f;
    float mrow[2] = { -INFINITY, -INFINITY };
    float lrow[2] = { 0.f, 0.f };

    // tile copy: 64x64h = 512 chunks; 2 per thread
    auto load_k = [&](int k0, int buf) {
        #pragma unroll
        for (int i = 0; i < 2; i++) {
            const int flat = tid + 256 * i;
            const int row = flat >> 3;
            const int c = flat & 7;
            cp_async16(smaddr(&KsBuf[buf][row * FSTR + c * 4]),
                       kb + (size_t)(k0 + row) * DK_ + c * 8);
        }
    };
    auto load_v = [&](int k0, int buf) {
        #pragma unroll
        for (int i = 0; i < 2; i++) {
            const int flat = tid + 256 * i;
            const int row = flat >> 3;
            const int c = flat & 7;
            cp_async16(smaddr(&VtBuf[buf][row * FSTR + c * 4]),
                       vtb + (size_t)row * S_ + k0 + c * 8);
        }
    };

    const int NT = 2 * qt + 2;
    const int rowmax = q0 + mb + 15;     // warp's last q row

    load_k(0, 0);
    load_v(0, 0);
    cp_commit();

    for (int kt = 0; kt < NT; kt++) {
        const int cur = kt & 1;
        cp_wait0();
        __syncthreads();
        if (kt + 1 < NT) {
            load_k((kt + 1) * 64, cur ^ 1);
            load_v((kt + 1) * 64, cur ^ 1);
            cp_commit();
        }
        const int k0 = kt * 64;
        if (k0 > rowmax) continue;       // tile entirely above warp's band

        const uint32_t* Ks = KsBuf[cur];
        const uint32_t* Vt = VtBuf[cur];

        // ---- S = Q @ K^T, fp16 accumulators ----
        uint32_t sl[8], sh[8];
        #pragma unroll
        for (int nt = 0; nt < 8; nt++) { sl[nt] = 0u; sh[nt] = 0u; }
        #pragma unroll
        for (int i = 0; i < 4; i++) {
            #pragma unroll
            for (int p = 0; p < 4; p++) {
                uint32_t b00, b01, b10, b11;
                ldsm_x4(b00, b01, b10, b11,
                        smaddr(&Ks[(p * 16 + brow) * FSTR + 8 * i + bcol]));
                mma_f16acc_16x8x16(sl[2*p], sh[2*p],
                                   qf[i][0], qf[i][1], qf[i][2], qf[i][3], b00, b01);
                mma_f16acc_16x8x16(sl[2*p+1], sh[2*p+1],
                                   qf[i][0], qf[i][1], qf[i][2], qf[i][3], b10, b11);
            }
        }

        // ---- causal mask (tiles intersecting the warp's band) ----
        if (k0 + 63 > q0 + mb) {
            const int r0 = q0 + mb + lr;
            const int r1 = r0 + 8;
            #pragma unroll
            for (int nt = 0; nt < 8; nt++) {
                const int cg = k0 + nt * 8 + 2 * lc;
                uint32_t v = sl[nt];
                if (cg     > r0) v = (v & 0xFFFF0000u) | 0x0000FC00u;
                if (cg + 1 > r0) v = (v & 0x0000FFFFu) | 0xFC000000u;
                sl[nt] = v;
                v = sh[nt];
                if (cg     > r1) v = (v & 0xFFFF0000u) | 0x0000FC00u;
                if (cg + 1 > r1) v = (v & 0x0000FFFFu) | 0xFC000000u;
                sh[nt] = v;
            }
        }

        // ---- row max (half2 tree, finish in fp32 + quad shfl) ----
        __half2 ml = u2h(sl[0]), mh = u2h(sh[0]);
        #pragma unroll
        for (int nt = 1; nt < 8; nt++) {
            ml = __hmax2(ml, u2h(sl[nt]));
            mh = __hmax2(mh, u2h(sh[nt]));
        }
        float m0 = fmaxf(__low2float(ml), __high2float(ml));
        float m1 = fmaxf(__low2float(mh), __high2float(mh));
        m0 = fmaxf(m0, __shfl_xor_sync(0xffffffffu, m0, 1));
        m0 = fmaxf(m0, __shfl_xor_sync(0xffffffffu, m0, 2));
        m1 = fmaxf(m1, __shfl_xor_sync(0xffffffffu, m1, 1));
        m1 = fmaxf(m1, __shfl_xor_sync(0xffffffffu, m1, 2));

        const float mnew0 = fmaxf(mrow[0], m0);
        const float mnew1 = fmaxf(mrow[1], m1);
        const float alpha0 = fexp2(mrow[0] - mnew0);
        const float alpha1 = fexp2(mrow[1] - mnew1);
        mrow[0] = mnew0;
        mrow[1] = mnew1;
        const __half2 mh0 = __float2half2_rn(mnew0);
        const __half2 mh1 = __float2half2_rn(mnew1);

        // ---- P = ex2(s - m), packed half2 (PV A-fragment order) ----
        uint32_t pf[4][4];
        #pragma unroll
        for (int i = 0; i < 4; i++) {
            pf[i][0] = exh2(h2u(__hsub2(u2h(sl[2*i]),   mh0)));
            pf[i][1] = exh2(h2u(__hsub2(u2h(sh[2*i]),   mh1)));
            pf[i][2] = exh2(h2u(__hsub2(u2h(sl[2*i+1]), mh0)));
            pf[i][3] = exh2(h2u(__hsub2(u2h(sh[2*i+1]), mh1)));
        }

        // ---- l partial sums (half2 tree, finish in fp32) ----
        {
            uint32_t a0 = hadd2u(pf[0][0], pf[1][0]);
            uint32_t a1 = hadd2u(pf[2][0], pf[3][0]);
            uint32_t a2 = hadd2u(pf[0][2], pf[1][2]);
            uint32_t a3 = hadd2u(pf[2][2], pf[3][2]);
            float ls0 = __low2float(u2h(a0)) + __high2float(u2h(a0))
                      + __low2float(u2h(a1)) + __high2float(u2h(a1))
                      + __low2float(u2h(a2)) + __high2float(u2h(a2))
                      + __low2float(u2h(a3)) + __high2float(u2h(a3));
            uint32_t b0 = hadd2u(pf[0][1], pf[1][1]);
            uint32_t b1 = hadd2u(pf[2][1], pf[3][1]);
            uint32_t b2 = hadd2u(pf[0][3], pf[1][3]);
            uint32_t b3 = hadd2u(pf[2][3], pf[3][3]);
            float ls1 = __low2float(u2h(b0)) + __high2float(u2h(b0))
                      + __low2float(u2h(b1)) + __high2float(u2h(b1))
                      + __low2float(u2h(b2)) + __high2float(u2h(b2))
                      + __low2float(u2h(b3)) + __high2float(u2h(b3));
            ls0 += __shfl_xor_sync(0xffffffffu, ls0, 1);
            ls0 += __shfl_xor_sync(0xffffffffu, ls0, 2);
            ls1 += __shfl_xor_sync(0xffffffffu, ls1, 1);
            ls1 += __shfl_xor_sync(0xffffffffu, ls1, 2);
            lrow[0] = lrow[0] * alpha0 + ls0;
            lrow[1] = lrow[1] * alpha1 + ls1;
        }

        #pragma unroll
        for (int nt = 0; nt < 8; nt++) {
            oacc[nt][0] *= alpha0; oacc[nt][1] *= alpha0;
            oacc[nt][2] *= alpha1; oacc[nt][3] *= alpha1;
        }

        // ---- O += P @ V (fp32 accum), V via ldmatrix ----
        #pragma unroll
        for (int i = 0; i < 4; i++) {
            #pragma unroll
            for (int p = 0; p < 4; p++) {
                uint32_t b00, b01, b10, b11;
                ldsm_x4(b00, b01, b10, b11,
                        smaddr(&Vt[(p * 16 + brow) * FSTR + 8 * i + bcol]));
                mma_f16_16x8x16(oacc[2*p][0], oacc[2*p][1], oacc[2*p][2], oacc[2*p][3],
                                pf[i][0], pf[i][1], pf[i][2], pf[i][3], b00, b01);
                mma_f16_16x8x16(oacc[2*p+1][0], oacc[2*p+1][1], oacc[2*p+1][2], oacc[2*p+1][3],
                                pf[i][0], pf[i][1], pf[i][2], pf[i][3], b10, b11);
            }
        }
    }

    // ---- finalize & write fp16 to [B,S,D] ----
    const float inv0 = 1.f / lrow[0];
    const float inv1 = 1.f / lrow[1];
    const int b = bh >> 4;
    const int h = bh & 15;
    const int r0 = q0 + mb + lr;
    __half* ob0 = o + ((size_t)b * S_ + r0)     * D_ + h * DK_;
    __half* ob1 = o + ((size_t)b * S_ + r0 + 8) * D_ + h * DK_;
    #pragma unroll
    for (int nt = 0; nt < 8; nt++) {
        const int c = nt * 8 + 2 * lc;
        *(__half2*)(ob0 + c) = __floats2half2_rn(oacc[nt][0] * inv0, oacc[nt][1] * inv0);
        *(__half2*)(ob1 + c) = __floats2half2_rn(oacc[nt][2] * inv1, oacc[nt][3] * inv1);
    }
}

// ---------------- launch ------------------------------------------------------
extern "C" void kernel_launch(void* const* d_in, const int* in_sizes, int n_in,
                              void* d_out, int out_size)
{
    const float* Q  = (const float*)d_in[0];
    const float* K  = (const float*)d_in[1];
    const float* V  = (const float*)d_in[2];
    const float* Wq = (const float*)d_in[3];
    const float* bq = (const float*)d_in[4];
    const float* Wk = (const float*)d_in[5];
    const float* bk = (const float*)d_in[6];
    const float* Wv = (const float*)d_in[7];
    const float* bv = (const float*)d_in[8];
    const float* Wo = (const float*)d_in[9];
    const float* bo = (const float*)d_in[10];
    // d_in[11] = mask (causal, known statically; ignored)

    __half *wq, *wk, *wv, *wo, *q, *k, *vt, *att;
    cudaGetSymbolAddress((void**)&wq,  g_wq);
    cudaGetSymbolAddress((void**)&wk,  g_wk);
    cudaGetSymbolAddress((void**)&wv,  g_wv);
    cudaGetSymbolAddress((void**)&wo,  g_wo);
    cudaGetSymbolAddress((void**)&q,   g_q);
    cudaGetSymbolAddress((void**)&k,   g_k);
    cudaGetSymbolAddress((void**)&vt,  g_vt);
    cudaGetSymbolAddress((void**)&att, g_att);

    // weight transpose+convert (inputs converted inline in the QKV GEMM)
    const dim3 wt_grid(D_ / 32, D_ / 32, 4);
    const dim3 wt_block(32, 8);
    convT_w4_kernel<<<wt_grid, wt_block>>>(Wq, Wk, Wv, Wo, wq, wk, wv, wo);

    // fused QKV projections (fp32 A inline-converted; Q pre-scaled; V transposed)
    const dim3 qkv_grid(D_ / 128, M_ROWS / 128, 3);   // (8, 64, 3)
    gemm_qkv_kernel<<<qkv_grid, 256>>>(Q, K, V, wq, wk, wv,
                                       bq, bk, bv, q, k, vt);

    // causal flash attention -> fp16 [B,S,D]
    const dim3 fa_grid(S_ / 128, B_ * H_);            // (16, 64)
    flash_attn_f16_kernel<<<fa_grid, 256>>>(q, k, vt, att);

    // output projection -> d_out (fp32)
    const dim3 out_grid(D_ / 128, M_ROWS / 128);
    gemm_out_kernel<<<out_grid, 256>>>(att, wo, bo, (float*)d_out);
}

// round 17
// speedup vs baseline: 1.1546x; 1.1546x over previous
#include <cuda_runtime.h>
#include <cuda_fp16.h>
#include <cstdint>

// Problem constants
#define B_ 4
#define S_ 2048
#define D_ 1024
#define H_ 16
#define DK_ 64
#define QSCALE_ 0.1803368801111137f   // (1/sqrt(64)) * log2(e)

#define M_ROWS (B_ * S_)   // 8192

// ---------------- scratch (device globals; no allocation allowed) ----------
__device__ __half g_qin[B_ * S_ * D_];
__device__ __half g_kin[B_ * S_ * D_];
__device__ __half g_vin[B_ * S_ * D_];
__device__ __half g_wq[D_ * D_];     // transposed [N][K]
__device__ __half g_wk[D_ * D_];
__device__ __half g_wv[D_ * D_];
__device__ __half g_wo[D_ * D_];
__device__ __half g_q[B_ * H_ * S_ * DK_];    // [B,H,S,DK], pre-scaled by QSCALE_
__device__ __half g_k[B_ * H_ * S_ * DK_];    // [B,H,S,DK]
__device__ __half g_vt[B_ * H_ * DK_ * S_];   // [B,H,DK,S]  (transposed V)
__device__ __half g_att[B_ * S_ * D_];        // [B,S,D]

// ---------------- helpers -----------------------------------------------------
__device__ __forceinline__ void mma_f16_16x8x16(
    float& c0, float& c1, float& c2, float& c3,
    uint32_t a0, uint32_t a1, uint32_t a2, uint32_t a3,
    uint32_t b0, uint32_t b1)
{
    asm volatile(
        "mma.sync.aligned.m16n8k16.row.col.f32.f16.f16.f32 "
        "{%0,%1,%2,%3}, {%4,%5,%6,%7}, {%8,%9}, {%0,%1,%2,%3};"
        : "+f"(c0), "+f"(c1), "+f"(c2), "+f"(c3)
        : "r"(a0), "r"(a1), "r"(a2), "r"(a3), "r"(b0), "r"(b1));
}

// fp16-accumulate variant: c0 = {row lr, cols 2lc,2lc+1}, c1 = {row lr+8, same}
__device__ __forceinline__ void mma_f16acc_16x8x16(
    uint32_t& c0, uint32_t& c1,
    uint32_t a0, uint32_t a1, uint32_t a2, uint32_t a3,
    uint32_t b0, uint32_t b1)
{
    asm volatile(
        "mma.sync.aligned.m16n8k16.row.col.f16.f16.f16.f16 "
        "{%0,%1}, {%2,%3,%4,%5}, {%6,%7}, {%0,%1};"
        : "+r"(c0), "+r"(c1)
        : "r"(a0), "r"(a1), "r"(a2), "r"(a3), "r"(b0), "r"(b1));
}

__device__ __forceinline__ void ldsm_x4(uint32_t& r0, uint32_t& r1,
                                        uint32_t& r2, uint32_t& r3, uint32_t a)
{
    asm volatile("ldmatrix.sync.aligned.m8n8.x4.shared.b16 {%0,%1,%2,%3}, [%4];"
                 : "=r"(r0), "=r"(r1), "=r"(r2), "=r"(r3) : "r"(a));
}

__device__ __forceinline__ void cp_async16(uint32_t smem_dst, const void* gsrc) {
    asm volatile("cp.async.cg.shared.global [%0], [%1], 16;"
                 :: "r"(smem_dst), "l"(gsrc));
}
__device__ __forceinline__ void cp_commit() {
    asm volatile("cp.async.commit_group;");
}
__device__ __forceinline__ void cp_wait0() {
    asm volatile("cp.async.wait_group 0;");
}
__device__ __forceinline__ uint32_t smaddr(const void* p) {
    return (uint32_t)__cvta_generic_to_shared(p);
}
__device__ __forceinline__ uint32_t h2u(__half2 h) {
    return *(uint32_t*)&h;
}
__device__ __forceinline__ __half2 u2h(uint32_t u) {
    return *(__half2*)&u;
}
__device__ __forceinline__ float fexp2(float x) {
    float y;
    asm("ex2.approx.f32 %0, %1;" : "=f"(y) : "f"(x));
    return y;
}
// ex2 on packed half2 (1 MUFU op for 2 values)
__device__ __forceinline__ uint32_t exh2(uint32_t u) {
    asm("ex2.approx.f16x2 %0, %0;" : "+r"(u));
    return u;
}
__device__ __forceinline__ uint32_t hadd2u(uint32_t a, uint32_t b) {
    return h2u(__hadd2(u2h(a), u2h(b)));
}

// ---------------- fused fp32 -> fp16 conversion (Q,K,V inputs) -----------------
// 4 independent float4 loads per thread (MLP=4 to hide DRAM latency).
__global__ __launch_bounds__(256)
void conv_h3_kernel(const float4* __restrict__ a, const float4* __restrict__ b,
                    const float4* __restrict__ c,
                    uint2* __restrict__ oa, uint2* __restrict__ ob,
                    uint2* __restrict__ oc, int n4)
{
    const int base = blockIdx.x * 1024 + threadIdx.x;
    const float4* in = blockIdx.y == 0 ? a : (blockIdx.y == 1 ? b : c);
    uint2* out       = blockIdx.y == 0 ? oa : (blockIdx.y == 1 ? ob : oc);
    float4 v[4];
    #pragma unroll
    for (int u = 0; u < 4; u++) {
        const int i = base + u * 256;
        if (i < n4) v[u] = in[i];
    }
    #pragma unroll
    for (int u = 0; u < 4; u++) {
        const int i = base + u * 256;
        if (i < n4) {
            uint2 r;
            r.x = h2u(__floats2half2_rn(v[u].x, v[u].y));
            r.y = h2u(__floats2half2_rn(v[u].z, v[u].w));
            out[i] = r;
        }
    }
}

// ---------------- fused fp32 [K][N] -> fp16 transposed [N][K] (4 weights) ------
__global__ __launch_bounds__(256)
void convT_w4_kernel(const float* __restrict__ W0, const float* __restrict__ W1,
                     const float* __restrict__ W2, const float* __restrict__ W3,
                     __half* __restrict__ T0, __half* __restrict__ T1,
                     __half* __restrict__ T2, __half* __restrict__ T3)
{
    __shared__ float t[32][33];
    const float* W = blockIdx.z == 0 ? W0 : (blockIdx.z == 1 ? W1 :
                     (blockIdx.z == 2 ? W2 : W3));
    __half* Wt     = blockIdx.z == 0 ? T0 : (blockIdx.z == 1 ? T1 :
                     (blockIdx.z == 2 ? T2 : T3));
    const int bn = blockIdx.x * 32;
    const int bk = blockIdx.y * 32;
    const int x = threadIdx.x;
    #pragma unroll
    for (int y = threadIdx.y; y < 32; y += 8)
        t[y][x] = W[(size_t)(bk + y) * D_ + bn + x];
    __syncthreads();
    #pragma unroll
    for (int y = threadIdx.y; y < 32; y += 8)
        Wt[(size_t)(bn + y) * D_ + bk + x] = __float2half(t[x][y]);
}

// ---------------- fp16 tensor-core GEMM core (cp.async + ldmatrix) -------------
// C = A[M,K] @ Wt[N,K]^T + bias.  (128x128, 256 threads; fp32 accumulate)
// mode 0: float* row-major [M,N]; mode 1: half* [B,H,S,DK]*out_scale;
// mode 2: half* [B,H,DK,S].
#define GBKH 32                 // K per stage, in halves
#define G_STR 20                // row stride in uint32(half2) units
#define G_WORDS (128 * G_STR)

__device__ __forceinline__
void gemm_f16_body(const __half* __restrict__ A, const __half* __restrict__ Wt,
                   const float* __restrict__ bias, void* __restrict__ Cout,
                   int mode, float out_scale,
                   uint32_t* As, uint32_t* Bs)
{
    const int K = D_, N = D_;
    const int tid  = threadIdx.x;
    const int warp = tid >> 5;
    const int lane = tid & 31;
    const int warpM = warp >> 2;
    const int warpN = warp & 3;
    const int lr = lane >> 2;
    const int lc = lane & 3;

    // ldmatrix lane->address selectors
    const int arow = ((lane >> 3) & 1) * 8 + (lane & 7);
    const int acol = ((lane >> 4) & 1) * 4;
    const int brow = ((lane >> 4) & 1) * 8 + (lane & 7);
    const int bcol = ((lane >> 3) & 1) * 4;

    const int block_row = blockIdx.y;
    const int block_col = blockIdx.x;

    const __half* Ab = A  + (size_t)block_row * 128 * K;
    const __half* Wb = Wt + (size_t)block_col * 128 * K;

    float acc[4][4][4];
    #pragma unroll
    for (int mt = 0; mt < 4; mt++)
        #pragma unroll
        for (int nt = 0; nt < 4; nt++)
            #pragma unroll
            for (int r = 0; r < 4; r++) acc[mt][nt][r] = 0.f;

    auto load_stage = [&](int k0, int buf) {
        uint32_t* Ad = As + buf * G_WORDS;
        uint32_t* Bd = Bs + buf * G_WORDS;
        #pragma unroll
        for (int u = 0; u < 2; u++) {
            const int flat = tid + u * 256;
            const int r = flat >> 2;
            const int c = (flat & 3);
            cp_async16(smaddr(Ad + r * G_STR + c * 4), Ab + (size_t)r * K + k0 + c * 8);
            cp_async16(smaddr(Bd + r * G_STR + c * 4), Wb + (size_t)r * K + k0 + c * 8);
        }
    };

    const int NK = K / GBKH;
    load_stage(0, 0);
    cp_commit();

    for (int it = 0; it < NK; it++) {
        cp_wait0();
        __syncthreads();
        if (it + 1 < NK) { load_stage((it + 1) * GBKH, (it + 1) & 1); cp_commit(); }

        const uint32_t* As_s = As + (it & 1) * G_WORDS;
        const uint32_t* Bs_s = Bs + (it & 1) * G_WORDS;

        #pragma unroll
        for (int ch = 0; ch < 2; ch++) {
            const int ks2 = ch * 8;
            uint32_t af[4][4];
            #pragma unroll
            for (int mt = 0; mt < 4; mt++) {
                const int m0 = warpM * 64 + mt * 16;
                ldsm_x4(af[mt][0], af[mt][1], af[mt][2], af[mt][3],
                        smaddr(&As_s[(m0 + arow) * G_STR + ks2 + acol]));
            }
            uint32_t bf[4][2];
            #pragma unroll
            for (int np = 0; np < 2; np++) {
                const int n0 = warpN * 32 + np * 16;
                ldsm_x4(bf[np * 2][0], bf[np * 2][1], bf[np * 2 + 1][0], bf[np * 2 + 1][1],
                        smaddr(&Bs_s[(n0 + brow) * G_STR + ks2 + bcol]));
            }
            #pragma unroll
            for (int mt = 0; mt < 4; mt++)
                #pragma unroll
                for (int nt = 0; nt < 4; nt++)
                    mma_f16_16x8x16(acc[mt][nt][0], acc[mt][nt][1],
                                    acc[mt][nt][2], acc[mt][nt][3],
                                    af[mt][0], af[mt][1], af[mt][2], af[mt][3],
                                    bf[nt][0], bf[nt][1]);
        }
    }

    #pragma unroll
    for (int mt = 0; mt < 4; mt++) {
        #pragma unroll
        for (int nt = 0; nt < 4; nt++) {
            const int n = block_col * 128 + warpN * 32 + nt * 8 + lc * 2;
            #pragma unroll
            for (int half_ = 0; half_ < 2; half_++) {
                const int m = block_row * 128 + warpM * 64 + mt * 16 + lr + half_ * 8;
                const float v0 = acc[mt][nt][half_ * 2 + 0] + bias[n];
                const float v1 = acc[mt][nt][half_ * 2 + 1] + bias[n + 1];
                if (mode == 0) {
                    float* C = (float*)Cout;
                    *(float2*)&C[(size_t)m * N + n] = make_float2(v0, v1);
                } else {
                    const int b  = m >> 11;
                    const int s  = m & 2047;
                    const int h  = n >> 6;
                    const int dk = n & 63;
                    __half* C = (__half*)Cout;
                    if (mode == 1) {
                        *(__half2*)(C + (((size_t)(b * H_ + h)) * S_ + s) * DK_ + dk)
                            = __floats2half2_rn(v0 * out_scale, v1 * out_scale);
                    } else {
                        C[(((size_t)(b * H_ + h)) * DK_ + dk)     * S_ + s] = __float2half(v0);
                        C[(((size_t)(b * H_ + h)) * DK_ + dk + 1) * S_ + s] = __float2half(v1);
                    }
                }
            }
        }
    }
}

// fused QKV projections (grid.z selects tensor)
__global__ __launch_bounds__(256)
void gemm_qkv_kernel(const __half* __restrict__ qin, const __half* __restrict__ kin,
                     const __half* __restrict__ vin,
                     const __half* __restrict__ wq, const __half* __restrict__ wk,
                     const __half* __restrict__ wv,
                     const float* __restrict__ bq, const float* __restrict__ bk,
                     const float* __restrict__ bv,
                     __half* __restrict__ q, __half* __restrict__ k,
                     __half* __restrict__ vt)
{
    __shared__ uint32_t As[2 * G_WORDS];
    __shared__ uint32_t Bs[2 * G_WORDS];
    const int z = blockIdx.z;
    if (z == 0)      gemm_f16_body(qin, wq, bq, q,  1, QSCALE_, As, Bs);
    else if (z == 1) gemm_f16_body(kin, wk, bk, k,  1, 1.0f,    As, Bs);
    else             gemm_f16_body(vin, wv, bv, vt, 2, 1.0f,    As, Bs);
}

// output projection
__global__ __launch_bounds__(256)
void gemm_out_kernel(const __half* __restrict__ att, const __half* __restrict__ wo,
                     const float* __restrict__ bo, float* __restrict__ out)
{
    __shared__ uint32_t As[2 * G_WORDS];
    __shared__ uint32_t Bs[2 * G_WORDS];
    gemm_f16_body(att, wo, bo, out, 0, 1.0f, As, Bs);
}

// ---------------- fp16 tensor-core causal flash attention ----------------------
// 128 q-rows per block, 8 warps x 16 rows, double-buffered 64-key K / V^T tiles.
// QK accumulates fp16; softmax in half2; PV accumulates fp32.
// Warps skip key tiles above their diagonal band.  (exact R12 form)
#define FSTR 36                  // 32 half2 + 4 pad
#define FTILE (64 * FSTR)

__global__ __launch_bounds__(256, 2)
void flash_attn_f16_kernel(const __half* __restrict__ q, const __half* __restrict__ k,
                           const __half* __restrict__ vt, __half* __restrict__ o)
{
    __shared__ uint32_t KsBuf[2][FTILE];     // also used (contiguously) to stage Q
    __shared__ uint32_t VtBuf[2][FTILE];

    const int qt  = gridDim.x - 1 - blockIdx.x;   // big blocks first
    const int bh  = blockIdx.y;
    const int tid = threadIdx.x;
    const int warp = tid >> 5;
    const int lane = tid & 31;
    const int lr = lane >> 2;
    const int lc = lane & 3;
    const int q0 = qt * 128;
    const int mb = warp * 16;

    // ldmatrix B-operand lane selectors
    const int brow = ((lane >> 4) & 1) * 8 + (lane & 7);
    const int bcol = ((lane >> 3) & 1) * 4;

    const __half* qb  = q  + (size_t)bh * S_ * DK_;
    const __half* kb  = k  + (size_t)bh * S_ * DK_;
    const __half* vtb = vt + (size_t)bh * DK_ * S_;

    // ---- stage Q tile (128x64h = 4608 words) across KsBuf[0..1]; 4 chunks/thr --
    uint32_t* Qs = &KsBuf[0][0];
    #pragma unroll
    for (int i = 0; i < 4; i++) {
        const int flat = tid + 256 * i;           // 0..1023
        const int row = flat >> 3;
        const int c = flat & 7;
        cp_async16(smaddr(Qs + row * FSTR + c * 4),
                   qb + (size_t)(q0 + row) * DK_ + c * 8);
    }
    cp_commit();
    cp_wait0();
    __syncthreads();

    uint32_t qf[4][4];
    #pragma unroll
    for (int i = 0; i < 4; i++) {
        qf[i][0] = Qs[(mb + lr)     * FSTR + 8 * i + lc];
        qf[i][1] = Qs[(mb + 8 + lr) * FSTR + 8 * i + lc];
        qf[i][2] = Qs[(mb + lr)     * FSTR + 8 * i + 4 + lc];
        qf[i][3] = Qs[(mb + 8 + lr) * FSTR + 8 * i + 4 + lc];
    }
    __syncthreads();   // Q reads done before K tiles overwrite

    float oacc[8][4];
    #pragma unroll
    for (int nt = 0; nt < 8; nt++)
        #pragma unroll
        for (int c = 0; c < 4; c++) oacc[nt][c] = 0.f;
    float mrow[2] = { -INFINITY, -INFINITY };
    float lrow[2] = { 0.f, 0.f };

    // tile copy: 64x64h = 512 chunks; 2 per thread
    auto load_k = [&](int k0, int buf) {
        #pragma unroll
        for (int i = 0; i < 2; i++) {
            const int flat = tid + 256 * i;
            const int row = flat >> 3;
            const int c = flat & 7;
            cp_async16(smaddr(&KsBuf[buf][row * FSTR + c * 4]),
                       kb + (size_t)(k0 + row) * DK_ + c * 8);
        }
    };
    auto load_v = [&](int k0, int buf) {
        #pragma unroll
        for (int i = 0; i < 2; i++) {
            const int flat = tid + 256 * i;
            const int row = flat >> 3;
            const int c = flat & 7;
            cp_async16(smaddr(&VtBuf[buf][row * FSTR + c * 4]),
                       vtb + (size_t)row * S_ + k0 + c * 8);
        }
    };

    const int NT = 2 * qt + 2;
    const int rowmax = q0 + mb + 15;     // warp's last q row

    load_k(0, 0);
    load_v(0, 0);
    cp_commit();

    for (int kt = 0; kt < NT; kt++) {
        const int cur = kt & 1;
        cp_wait0();
        __syncthreads();
        if (kt + 1 < NT) {
            load_k((kt + 1) * 64, cur ^ 1);
            load_v((kt + 1) * 64, cur ^ 1);
            cp_commit();
        }
        const int k0 = kt * 64;
        if (k0 > rowmax) continue;       // tile entirely above warp's band

        const uint32_t* Ks = KsBuf[cur];
        const uint32_t* Vt = VtBuf[cur];

        // ---- S = Q @ K^T, fp16 accumulators ----
        uint32_t sl[8], sh[8];
        #pragma unroll
        for (int nt = 0; nt < 8; nt++) { sl[nt] = 0u; sh[nt] = 0u; }
        #pragma unroll
        for (int i = 0; i < 4; i++) {
            #pragma unroll
            for (int p = 0; p < 4; p++) {
                uint32_t b00, b01, b10, b11;
                ldsm_x4(b00, b01, b10, b11,
                        smaddr(&Ks[(p * 16 + brow) * FSTR + 8 * i + bcol]));
                mma_f16acc_16x8x16(sl[2*p], sh[2*p],
                                   qf[i][0], qf[i][1], qf[i][2], qf[i][3], b00, b01);
                mma_f16acc_16x8x16(sl[2*p+1], sh[2*p+1],
                                   qf[i][0], qf[i][1], qf[i][2], qf[i][3], b10, b11);
            }
        }

        // ---- causal mask (tiles intersecting the warp's band) ----
        if (k0 + 63 > q0 + mb) {
            const int r0 = q0 + mb + lr;
            const int r1 = r0 + 8;
            #pragma unroll
            for (int nt = 0; nt < 8; nt++) {
                const int cg = k0 + nt * 8 + 2 * lc;
                uint32_t v = sl[nt];
                if (cg     > r0) v = (v & 0xFFFF0000u) | 0x0000FC00u;
                if (cg + 1 > r0) v = (v & 0x0000FFFFu) | 0xFC000000u;
                sl[nt] = v;
                v = sh[nt];
                if (cg     > r1) v = (v & 0xFFFF0000u) | 0x0000FC00u;
                if (cg + 1 > r1) v = (v & 0x0000FFFFu) | 0xFC000000u;
                sh[nt] = v;
            }
        }

        // ---- row max (half2 tree, finish in fp32 + quad shfl) ----
        __half2 ml = u2h(sl[0]), mh = u2h(sh[0]);
        #pragma unroll
        for (int nt = 1; nt < 8; nt++) {
            ml = __hmax2(ml, u2h(sl[nt]));
            mh = __hmax2(mh, u2h(sh[nt]));
        }
        float m0 = fmaxf(__low2float(ml), __high2float(ml));
        float m1 = fmaxf(__low2float(mh), __high2float(mh));
        m0 = fmaxf(m0, __shfl_xor_sync(0xffffffffu, m0, 1));
        m0 = fmaxf(m0, __shfl_xor_sync(0xffffffffu, m0, 2));
        m1 = fmaxf(m1, __shfl_xor_sync(0xffffffffu, m1, 1));
        m1 = fmaxf(m1, __shfl_xor_sync(0xffffffffu, m1, 2));

        const float mnew0 = fmaxf(mrow[0], m0);
        const float mnew1 = fmaxf(mrow[1], m1);
        const float alpha0 = fexp2(mrow[0] - mnew0);
        const float alpha1 = fexp2(mrow[1] - mnew1);
        mrow[0] = mnew0;
        mrow[1] = mnew1;
        const __half2 mh0 = __float2half2_rn(mnew0);
        const __half2 mh1 = __float2half2_rn(mnew1);

        // ---- P = ex2(s - m), packed half2 (PV A-fragment order) ----
        uint32_t pf[4][4];
        #pragma unroll
        for (int i = 0; i < 4; i++) {
            pf[i][0] = exh2(h2u(__hsub2(u2h(sl[2*i]),   mh0)));
            pf[i][1] = exh2(h2u(__hsub2(u2h(sh[2*i]),   mh1)));
            pf[i][2] = exh2(h2u(__hsub2(u2h(sl[2*i+1]), mh0)));
            pf[i][3] = exh2(h2u(__hsub2(u2h(sh[2*i+1]), mh1)));
        }

        // ---- l partial sums (half2 tree, finish in fp32) ----
        {
            uint32_t a0 = hadd2u(pf[0][0], pf[1][0]);
            uint32_t a1 = hadd2u(pf[2][0], pf[3][0]);
            uint32_t a2 = hadd2u(pf[0][2], pf[1][2]);
            uint32_t a3 = hadd2u(pf[2][2], pf[3][2]);
            float ls0 = __low2float(u2h(a0)) + __high2float(u2h(a0))
                      + __low2float(u2h(a1)) + __high2float(u2h(a1))
                      + __low2float(u2h(a2)) + __high2float(u2h(a2))
                      + __low2float(u2h(a3)) + __high2float(u2h(a3));
            uint32_t b0 = hadd2u(pf[0][1], pf[1][1]);
            uint32_t b1 = hadd2u(pf[2][1], pf[3][1]);
            uint32_t b2 = hadd2u(pf[0][3], pf[1][3]);
            uint32_t b3 = hadd2u(pf[2][3], pf[3][3]);
            float ls1 = __low2float(u2h(b0)) + __high2float(u2h(b0))
                      + __low2float(u2h(b1)) + __high2float(u2h(b1))
                      + __low2float(u2h(b2)) + __high2float(u2h(b2))
                      + __low2float(u2h(b3)) + __high2float(u2h(b3));
            ls0 += __shfl_xor_sync(0xffffffffu, ls0, 1);
            ls0 += __shfl_xor_sync(0xffffffffu, ls0, 2);
            ls1 += __shfl_xor_sync(0xffffffffu, ls1, 1);
            ls1 += __shfl_xor_sync(0xffffffffu, ls1, 2);
            lrow[0] = lrow[0] * alpha0 + ls0;
            lrow[1] = lrow[1] * alpha1 + ls1;
        }

        #pragma unroll
        for (int nt = 0; nt < 8; nt++) {
            oacc[nt][0] *= alpha0; oacc[nt][1] *= alpha0;
            oacc[nt][2] *= alpha1; oacc[nt][3] *= alpha1;
        }

        // ---- O += P @ V (fp32 accum), V via ldmatrix ----
        #pragma unroll
        for (int i = 0; i < 4; i++) {
            #pragma unroll
            for (int p = 0; p < 4; p++) {
                uint32_t b00, b01, b10, b11;
                ldsm_x4(b00, b01, b10, b11,
                        smaddr(&Vt[(p * 16 + brow) * FSTR + 8 * i + bcol]));
                mma_f16_16x8x16(oacc[2*p][0], oacc[2*p][1], oacc[2*p][2], oacc[2*p][3],
                                pf[i][0], pf[i][1], pf[i][2], pf[i][3], b00, b01);
                mma_f16_16x8x16(oacc[2*p+1][0], oacc[2*p+1][1], oacc[2*p+1][2], oacc[2*p+1][3],
                                pf[i][0], pf[i][1], pf[i][2], pf[i][3], b10, b11);
            }
        }
    }

    // ---- finalize & write fp16 to [B,S,D] ----
    const float inv0 = 1.f / lrow[0];
    const float inv1 = 1.f / lrow[1];
    const int b = bh >> 4;
    const int h = bh & 15;
    const int r0 = q0 + mb + lr;
    __half* ob0 = o + ((size_t)b * S_ + r0)     * D_ + h * DK_;
    __half* ob1 = o + ((size_t)b * S_ + r0 + 8) * D_ + h * DK_;
    #pragma unroll
    for (int nt = 0; nt < 8; nt++) {
        const int c = nt * 8 + 2 * lc;
        *(__half2*)(ob0 + c) = __floats2half2_rn(oacc[nt][0] * inv0, oacc[nt][1] * inv0);
        *(__half2*)(ob1 + c) = __floats2half2_rn(oacc[nt][2] * inv1, oacc[nt][3] * inv1);
    }
}

// ---------------- launch ------------------------------------------------------
extern "C" void kernel_launch(void* const* d_in, const int* in_sizes, int n_in,
                              void* d_out, int out_size)
{
    const float* Q  = (const float*)d_in[0];
    const float* K  = (const float*)d_in[1];
    const float* V  = (const float*)d_in[2];
    const float* Wq = (const float*)d_in[3];
    const float* bq = (const float*)d_in[4];
    const float* Wk = (const float*)d_in[5];
    const float* bk = (const float*)d_in[6];
    const float* Wv = (const float*)d_in[7];
    const float* bv = (const float*)d_in[8];
    const float* Wo = (const float*)d_in[9];
    const float* bo = (const float*)d_in[10];
    // d_in[11] = mask (causal, known statically; ignored)

    __half *qin, *kin, *vin, *wq, *wk, *wv, *wo, *q, *k, *vt, *att;
    cudaGetSymbolAddress((void**)&qin, g_qin);
    cudaGetSymbolAddress((void**)&kin, g_kin);
    cudaGetSymbolAddress((void**)&vin, g_vin);
    cudaGetSymbolAddress((void**)&wq,  g_wq);
    cudaGetSymbolAddress((void**)&wk,  g_wk);
    cudaGetSymbolAddress((void**)&wv,  g_wv);
    cudaGetSymbolAddress((void**)&wo,  g_wo);
    cudaGetSymbolAddress((void**)&q,   g_q);
    cudaGetSymbolAddress((void**)&k,   g_k);
    cudaGetSymbolAddress((void**)&vt,  g_vt);
    cudaGetSymbolAddress((void**)&att, g_att);

    // fused conversions (4x float4 per thread, MLP=4)
    const int n4_in = (B_ * S_ * D_) / 4;
    const dim3 c3_grid((n4_in + 1023) / 1024, 3);
    conv_h3_kernel<<<c3_grid, 256>>>((const float4*)Q, (const float4*)K,
                                     (const float4*)V, (uint2*)qin, (uint2*)kin,
                                     (uint2*)vin, n4_in);
    const dim3 wt_grid(D_ / 32, D_ / 32, 4);
    const dim3 wt_block(32, 8);
    convT_w4_kernel<<<wt_grid, wt_block>>>(Wq, Wk, Wv, Wo, wq, wk, wv, wo);

    // fused QKV projections (Q pre-scaled into log2 domain; V transposed)
    const dim3 qkv_grid(D_ / 128, M_ROWS / 128, 3);   // (8, 64, 3)
    gemm_qkv_kernel<<<qkv_grid, 256>>>(qin, kin, vin, wq, wk, wv,
                                       bq, bk, bv, q, k, vt);

    // causal flash attention -> fp16 [B,S,D]
    const dim3 fa_grid(S_ / 128, B_ * H_);            // (16, 64)
    flash_attn_f16_kernel<<<fa_grid, 256>>>(q, k, vt, att);

    // output projection -> d_out (fp32)
    const dim3 out_grid(D_ / 128, M_ROWS / 128);
    gemm_out_kernel<<<out_grid, 256>>>(att, wo, bo, (float*)d_out);
}